// round 11
// baseline (speedup 1.0000x reference)
#include <cuda_runtime.h>
#include <cuda_bf16.h>
#include <mma.h>
#include <cstdint>

using namespace nvcuda;

// Tropical (max-plus) Gram matrix via log-sum-exp GEMM on HMMA (wmma bf16).
// H[i,j] = m_i + m_j + log( sum_k e^{L(|W_ik|-m_i)} e^{L(|W_jk|-m_j)} ) / L
// R11 = R9 (K-split, 2 CTAs/SM, raw partial stores + finish kernel)
//     + R8's register double-buffered fragments (fits 128-reg cap: 64 acc
//       + 16 A + 32 B) + register-resident single-pass prep kernel.
// FP8 is unusable here: per-FACTOR underflow (e4m3 floor 2^-9) zeroes all
// off-diagonal dominant terms -> bf16 is the right operand type.

constexpr int N_DIM = 2048;
constexpr int K_DIM = 10000;
constexpr int KHALF_PAD = 5056;                // 79 * 64
constexpr int K_PAD = 2 * KHALF_PAD;           // 10112
constexpr float LMB = 2600.0f;
constexpr int NTILES = 16;
constexpr int NPAIRS = 136;
constexpr int KTS  = 64;                       // k per pipeline stage
constexpr int NSTG = KHALF_PAD / KTS;          // 79
constexpr int ESTR = 72;                       // smem row stride (bf16) = 144B
constexpr int STAGE_BYTES = 128 * ESTR * 2;    // 18432 per operand
constexpr int NBUF = 3;
constexpr int PIPE_BYTES = NBUF * 2 * STAGE_BYTES;   // 110592
constexpr int NTHR = 256;
constexpr int LDT = 133;                       // finish-kernel tile stride
constexpr int FIN_SMEM = 128 * LDT * 4;        // 68096

__device__ __nv_bfloat16 g_E[(size_t)N_DIM * K_PAD];
__device__ float g_m[N_DIM];
__device__ float g_P[(size_t)N_DIM * N_DIM];   // partial sums, K-half 1

__device__ __forceinline__ uint32_t smem_u32(const void* p) {
    uint32_t a;
    asm("{ .reg .u64 t; cvta.to.shared.u64 t, %1; cvt.u32.u64 %0, t; }" : "=r"(a) : "l"(p));
    return a;
}
__device__ __forceinline__ void cp16(uint32_t dst, const void* src) {
    asm volatile("cp.async.cg.shared.global [%0], [%1], 16;" :: "r"(dst), "l"(src) : "memory");
}
__device__ __forceinline__ void cp_commit() {
    asm volatile("cp.async.commit_group;" ::: "memory");
}
template <int N>
__device__ __forceinline__ void cp_wait() {
    asm volatile("cp.async.wait_group %0;" :: "n"(N) : "memory");
}

// ------- kernel 1: reg-resident rowmax + E = bf16(exp(L*(|W|-m))) -------
__global__ void prep_kernel(const float* __restrict__ W) {
    const int i = blockIdx.x;
    const int t = threadIdx.x;
    const float4* row4 = (const float4*)(W + (size_t)i * K_DIM);

    // hold the whole row in registers (<= 10 float4 per thread)
    float4 v[10];
    float m = 0.0f;
#pragma unroll
    for (int q = 0; q < 10; ++q) {
        int c = t + 256 * q;
        if (c < K_DIM / 4) {
            v[q] = row4[c];
            m = fmaxf(m, fmaxf(fmaxf(fabsf(v[q].x), fabsf(v[q].y)),
                               fmaxf(fabsf(v[q].z), fabsf(v[q].w))));
        }
    }
#pragma unroll
    for (int o = 16; o; o >>= 1) m = fmaxf(m, __shfl_xor_sync(~0u, m, o));
    __shared__ float red[8];
    __shared__ float mbc;
    if ((t & 31) == 0) red[t >> 5] = m;
    __syncthreads();
    if (t < 8) {
        float w = red[t];
#pragma unroll
        for (int o = 4; o; o >>= 1) w = fmaxf(w, __shfl_xor_sync(0xffu, w, o));
        if (t == 0) { mbc = w; g_m[i] = w; }
    }
    __syncthreads();
    const float mv = mbc;

    __nv_bfloat16* erow = g_E + (size_t)i * K_PAD;
#pragma unroll
    for (int q = 0; q < 10; ++q) {
        int c = t + 256 * q;
        if (c < K_DIM / 4) {
            __nv_bfloat16 o[4];
            o[0] = __float2bfloat16(__expf((fabsf(v[q].x) - mv) * LMB));
            o[1] = __float2bfloat16(__expf((fabsf(v[q].y) - mv) * LMB));
            o[2] = __float2bfloat16(__expf((fabsf(v[q].z) - mv) * LMB));
            o[3] = __float2bfloat16(__expf((fabsf(v[q].w) - mv) * LMB));
            *(uint2*)(erow + c * 4) = *(const uint2*)o;
        }
    }
    // zero padding K_DIM..K_PAD (112 elems = 56 u32 writes)
    if (t < 56) *(uint32_t*)(erow + K_DIM + 2 * t) = 0u;
}

// ------- kernel 2: wmma bf16 GEMM (reg double-buffered) -> raw partials -------
__global__ void __launch_bounds__(NTHR, 2)
lse_gemm_kernel(float* __restrict__ H)
{
    extern __shared__ char smem[];
    const uint32_t sb = smem_u32(smem);
    const int tid = (int)threadIdx.x;
    const int wid = tid >> 5;

    int rem = (int)blockIdx.x;
    int ti = 0;
    while (rem >= NTILES - ti) { rem -= NTILES - ti; ++ti; }
    const int tj = ti + rem;
    const int gi = ti * 128, gj = tj * 128;
    const int ky = (int)blockIdx.y;
    const size_t kbase = (size_t)ky * KHALF_PAD;
    float* out = ky ? g_P : H;

    // warp grid 4(m) x 2(n): each warp 32(m) x 64(n)
    const int m0 = (wid & 3) * 32;
    const int n0 = (wid >> 2) * 64;

    wmma::fragment<wmma::accumulator, 16, 16, 16, float> acc[2][4];
#pragma unroll
    for (int a = 0; a < 2; ++a)
#pragma unroll
        for (int b = 0; b < 4; ++b) wmma::fill_fragment(acc[a][b], 0.0f);

    // stage prefetch: 2048 x 16B chunks by 256 threads (8 each)
    auto prefetch = [&](int s) {
        const int buf = s % NBUF;
        const uint32_t abase = sb + (uint32_t)buf * 2 * STAGE_BYTES;
        const uint32_t bbase = abase + STAGE_BYTES;
#pragma unroll
        for (int q = 0; q < 8; ++q) {
            int c = tid + NTHR * q;           // 0..2047
            int isB = c >> 10;
            int cc = c & 1023;
            int row = cc >> 3, sub = cc & 7;  // 8 x 16B = 128B per row
            uint32_t dst = (isB ? bbase : abase) + (uint32_t)(row * (ESTR * 2) + sub * 16);
            const __nv_bfloat16* src =
                g_E + (size_t)((isB ? gj : gi) + row) * K_PAD + kbase + (size_t)s * KTS + sub * 8;
            cp16(dst, src);
        }
        cp_commit();
    };

    prefetch(0); prefetch(1);

    typedef wmma::fragment<wmma::matrix_a, 16, 16, 16, __nv_bfloat16, wmma::row_major> FragA;
    typedef wmma::fragment<wmma::matrix_b, 16, 16, 16, __nv_bfloat16, wmma::col_major> FragB;

#pragma unroll 1
    for (int s = 0; s < NSTG; ++s) {
        if (s >= NSTG - 1) cp_wait<0>();
        else               cp_wait<1>();
        __syncthreads();
        if (s + 2 < NSTG) prefetch(s + 2);

        const int buf = s % NBUF;
        const __nv_bfloat16* A = (const __nv_bfloat16*)(smem + buf * 2 * STAGE_BYTES);
        const __nv_bfloat16* B = (const __nv_bfloat16*)(smem + buf * 2 * STAGE_BYTES + STAGE_BYTES);

        FragA af[2][2];
        FragB bfr[2][4];
        // preload k-step 0 into reg-buffer 0
#pragma unroll
        for (int a = 0; a < 2; ++a)
            wmma::load_matrix_sync(af[0][a], A + (m0 + a * 16) * ESTR, ESTR);
#pragma unroll
        for (int b = 0; b < 4; ++b)
            wmma::load_matrix_sync(bfr[0][b], B + (n0 + b * 16) * ESTR, ESTR);

#pragma unroll
        for (int kki = 0; kki < 4; ++kki) {
            const int cb = kki & 1, nb = cb ^ 1;
            if (kki < 3) {
                const int kk = (kki + 1) * 16;
#pragma unroll
                for (int a = 0; a < 2; ++a)
                    wmma::load_matrix_sync(af[nb][a], A + (m0 + a * 16) * ESTR + kk, ESTR);
#pragma unroll
                for (int b = 0; b < 4; ++b)
                    wmma::load_matrix_sync(bfr[nb][b], B + (n0 + b * 16) * ESTR + kk, ESTR);
            }
#pragma unroll
            for (int a = 0; a < 2; ++a)
#pragma unroll
                for (int b = 0; b < 4; ++b)
                    wmma::mma_sync(acc[a][b], af[cb][a], bfr[cb][b], acc[a][b]);
        }
    }

    // store raw partial sums directly to global
#pragma unroll
    for (int a = 0; a < 2; ++a)
#pragma unroll
        for (int b = 0; b < 4; ++b)
            wmma::store_matrix_sync(out + (size_t)(gi + m0 + a * 16) * N_DIM + gj + n0 + b * 16,
                                    acc[a][b], N_DIM, wmma::mem_row_major);
}

// ------- kernel 3: H = m_i + m_j + log(P0+P1)/L, + mirror -------
__global__ void finish_kernel(float* __restrict__ H)
{
    extern __shared__ float tile[];   // [128][LDT]
    __shared__ float mi_s[128], mj_s[128];
    const int tid = (int)threadIdx.x;

    int rem = (int)blockIdx.x;
    int ti = 0;
    while (rem >= NTILES - ti) { rem -= NTILES - ti; ++ti; }
    const int tj = ti + rem;
    const int gi = ti * 128, gj = tj * 128;

    if (tid < 128) { mi_s[tid] = g_m[gi + tid]; mj_s[tid] = g_m[gj + tid]; }
    __syncthreads();

    const float invL = 1.0f / LMB;
#pragma unroll 4
    for (int it = 0; it < 16; ++it) {
        int idx = tid + it * 256;
        int r = idx >> 5, c4 = (idx & 31) * 4;
        size_t go = (size_t)(gi + r) * N_DIM + gj + c4;
        float4 p0 = *(const float4*)&H[go];
        float4 p1 = *(const float4*)&g_P[go];
        float base = mi_s[r];
        float4 v;
        v.x = base + mj_s[c4 + 0] + __logf(p0.x + p1.x) * invL;
        v.y = base + mj_s[c4 + 1] + __logf(p0.y + p1.y) * invL;
        v.z = base + mj_s[c4 + 2] + __logf(p0.z + p1.z) * invL;
        v.w = base + mj_s[c4 + 3] + __logf(p0.w + p1.w) * invL;
        tile[r * LDT + c4 + 0] = v.x;
        tile[r * LDT + c4 + 1] = v.y;
        tile[r * LDT + c4 + 2] = v.z;
        tile[r * LDT + c4 + 3] = v.w;
        *(float4*)&H[go] = v;
    }

    if (ti == tj) return;

    __syncthreads();
#pragma unroll 4
    for (int it = 0; it < 16; ++it) {
        int idx = tid + it * 256;
        int r = idx >> 5, c4 = (idx & 31) * 4;
        float4 v;
        v.x = tile[(c4 + 0) * LDT + r];
        v.y = tile[(c4 + 1) * LDT + r];
        v.z = tile[(c4 + 2) * LDT + r];
        v.w = tile[(c4 + 3) * LDT + r];
        *(float4*)&H[(size_t)(gj + r) * N_DIM + gi + c4] = v;
    }
}

// ---------------- launcher ----------------
extern "C" void kernel_launch(void* const* d_in, const int* in_sizes, int n_in,
                              void* d_out, int out_size) {
    const float* W = (const float*)d_in[0];
    float* H = (float*)d_out;

    cudaFuncSetAttribute(lse_gemm_kernel, cudaFuncAttributeMaxDynamicSharedMemorySize, PIPE_BYTES);
    cudaFuncSetAttribute(finish_kernel, cudaFuncAttributeMaxDynamicSharedMemorySize, FIN_SMEM);

    prep_kernel<<<N_DIM, 256>>>(W);
    dim3 gg(NPAIRS, 2);
    lse_gemm_kernel<<<gg, NTHR, PIPE_BYTES>>>(H);
    finish_kernel<<<NPAIRS, 256, FIN_SMEM>>>(H);
}